// round 6
// baseline (speedup 1.0000x reference)
#include <cuda_runtime.h>
#include <cuda_fp16.h>
#include <math.h>
#include <stdint.h>

#define SS 128
#define BB 1024
#define EE 256
#define HH 256
#define H3 768
#define FF 512
#define SB (SS*BB)          // 131072
#define VV 50000

#define AST 24     // chunk-tile row stride (halves): 16 + pad
#define WST 264    // full-K tile row stride (halves): 256 + pad

// ---------------- device scratch (no allocs allowed) ----------------
__device__ __half g_emb16[(size_t)VV * EE];
__device__ __half g_Wih16[2][H3 * EE];
__device__ __half g_Whh16[2][H3 * HH];
__device__ __half g_WwT16[FF * FF];           // [n][k] = Ww[k][n]
__device__ __half g_gi16[2][(size_t)SB * H3];
__device__ __half g_f16[(size_t)SB * FF];
__device__ float  g_h32[2][2][BB * HH];       // [pingpong][dir]
__device__ __half g_h16[2][2][BB * HH];
__device__ float  g_scores_pre[SB];
__device__ float  g_alpha[SB];
__device__ unsigned g_gcnt[16 * 32];          // per-group barrier counters (128B apart)
__device__ volatile unsigned g_ggen[16 * 32];

// ---------------- helpers ----------------
__device__ __forceinline__ uint32_t smem_u32(const void* p) {
    return (uint32_t)__cvta_generic_to_shared(p);
}
__device__ __forceinline__ void ldsm4(uint32_t& r0, uint32_t& r1, uint32_t& r2, uint32_t& r3, uint32_t a) {
    asm volatile("ldmatrix.sync.aligned.m8n8.x4.shared.b16 {%0,%1,%2,%3},[%4];"
                 : "=r"(r0), "=r"(r1), "=r"(r2), "=r"(r3) : "r"(a));
}
__device__ __forceinline__ void mma16816(float* c, const uint32_t* a, uint32_t b0, uint32_t b1) {
    asm volatile("mma.sync.aligned.m16n8k16.row.col.f32.f16.f16.f32 "
                 "{%0,%1,%2,%3},{%4,%5,%6,%7},{%8,%9},{%0,%1,%2,%3};"
                 : "+f"(c[0]), "+f"(c[1]), "+f"(c[2]), "+f"(c[3])
                 : "r"(a[0]), "r"(a[1]), "r"(a[2]), "r"(a[3]), "r"(b0), "r"(b1));
}
__device__ __forceinline__ float sigmoidf_(float x) { return 1.0f / (1.0f + expf(-x)); }

// Ws: 96 cols, K=256 full, gate/j interleaved so mma frags hold complete triples.
// col c: wslot=c/48, cl=c%48, nf=cl/8, q=cl&7, gate=nf%3, grp=nf/3
//   -> W row = gate*HH + j0 + wslot*16 + grp*8 + q
__device__ __forceinline__ void load_Ws(__half* Ws, const __half* W16, int j0, int tid) {
    for (int i = tid; i < 96 * 32; i += 256) {
        const int c = i >> 5, seg = i & 31;
        const int wslot = c / 48, cl = c % 48, nf = cl >> 3, q = cl & 7;
        const int gate = nf % 3, grp = nf / 3;
        const int wrow = gate * HH + j0 + wslot * 16 + grp * 8 + q;
        uint4 v = *(const uint4*)(W16 + (size_t)wrow * 256 + seg * 8);
        *(uint4*)(Ws + c * WST + seg * 8) = v;
    }
}

// warp tile 32x48 (mf=2, nf=6), one k=16 chunk. 2 ldsm4(A) + 3 ldsm4(B) -> 12 mma.
template<int STRIDE>
__device__ __forceinline__ void mma_chunk_32x48(const __half* Atile, const __half* Ws,
                                                int kcA, int kcW, int wm0, int wn0c,
                                                int lane, float (&c)[2][6][4]) {
    uint32_t a[2][4];
    #pragma unroll
    for (int mf = 0; mf < 2; mf++) {
        uint32_t addr = smem_u32(Atile + (wm0 + mf * 16 + (lane & 15)) * STRIDE + kcA + ((lane >> 4) << 3));
        ldsm4(a[mf][0], a[mf][1], a[mf][2], a[mf][3], addr);
    }
    uint32_t b[6][2];
    #pragma unroll
    for (int p = 0; p < 3; p++) {
        uint32_t addr = smem_u32(Ws + (wn0c + p * 16 + (lane & 15)) * WST + kcW + ((lane >> 4) << 3));
        uint32_t r0, r1, r2, r3;
        ldsm4(r0, r1, r2, r3, addr);
        b[2*p][0] = r0; b[2*p+1][0] = r1; b[2*p][1] = r2; b[2*p+1][1] = r3;
    }
    #pragma unroll
    for (int mf = 0; mf < 2; mf++)
        #pragma unroll
        for (int nf = 0; nf < 6; nf++)
            mma16816(c[mf][nf], a[mf], b[nf][0], b[nf][1]);
}

// ---------------- conversions + init ----------------
__global__ void conv_main(const float* __restrict__ emb,
                          const float* __restrict__ Wihf, const float* __restrict__ Wihb,
                          const float* __restrict__ Whhf, const float* __restrict__ Whhb,
                          const float* __restrict__ Ww,   const float* __restrict__ hidden) {
    int i = blockIdx.x * blockDim.x + threadIdx.x;
    int st = gridDim.x * blockDim.x;
    for (size_t j = i; j < (size_t)VV * EE; j += st) g_emb16[j] = __float2half(emb[j]);
    for (int j = i; j < H3 * EE; j += st) {
        g_Wih16[0][j] = __float2half(Wihf[j]);
        g_Wih16[1][j] = __float2half(Wihb[j]);
        g_Whh16[0][j] = __float2half(Whhf[j]);
        g_Whh16[1][j] = __float2half(Whhb[j]);
    }
    for (int j = i; j < FF * FF; j += st) {
        int n = j / FF, k = j % FF;
        g_WwT16[j] = __float2half(Ww[(size_t)k * FF + n]);
    }
    for (int j = i; j < 2 * BB * HH; j += st) {
        float v = hidden[j];
        (&g_h32[0][0][0])[j] = v;
        (&g_h16[0][0][0])[j] = __float2half(v);
    }
    for (int j = i; j < SB; j += st) g_scores_pre[j] = 0.0f;
    if (i < 16 * 32) { g_gcnt[i] = 0u; }
}

// ---------------- gi = gather(emb,tokens) @ W_ih^T + b_ih  (fp16 out) ----------------
// grid (SB/128, 8, 2); block tile 128 x 96 (gate/j interleaved cols)
__global__ void __launch_bounds__(256) gi_mma(const int* __restrict__ tokens,
                                              const float* __restrict__ bif,
                                              const float* __restrict__ bib) {
    extern __shared__ unsigned char smem[];
    __half* Ws = (__half*)smem;                        // 96*WST*2 = 50688
    __half* As = (__half*)(smem + 96 * WST * 2);       // 2 * 128*AST*2 = 12288
    __shared__ int tok[128];

    const int tid = threadIdx.x, lane = tid & 31, wid = tid >> 5;
    const int m0 = blockIdx.x * 128, j0 = blockIdx.y * 32, dir = blockIdx.z;
    const int wm0 = (wid >> 1) * 32, wn0c = (wid & 1) * 48;

    load_Ws(Ws, g_Wih16[dir], j0, tid);
    if (tid < 128) tok[tid] = tokens[m0 + tid];
    __syncthreads();

    const int arow = tid >> 1, apart = tid & 1;
    const __half* esrc = g_emb16 + (size_t)tok[arow] * EE + apart * 8;
    uint4 pref = *(const uint4*)esrc;

    float c[2][6][4] = {};
    for (int t = 0; t < 16; t++) {
        *(uint4*)(As + (t & 1) * 128 * AST + arow * AST + apart * 8) = pref;
        __syncthreads();
        if (t < 15) pref = *(const uint4*)(esrc + (t + 1) * 16);
        mma_chunk_32x48<AST>(As + (t & 1) * 128 * AST, Ws, 0, t * 16, wm0, wn0c, lane, c);
    }

    const float* bias = dir ? bib : bif;
    __half* go = g_gi16[dir];
    const int jbase = j0 + (wid & 1) * 16 + (lane & 3) * 2;
    #pragma unroll
    for (int mf = 0; mf < 2; mf++) {
        const int r0 = m0 + wm0 + mf * 16 + (lane >> 2);
        #pragma unroll
        for (int nf = 0; nf < 6; nf++) {
            const int gate = nf % 3, grp = nf / 3;
            const int n = gate * HH + jbase + grp * 8;
            const float b0 = bias[n], b1 = bias[n + 1];
            *(__half2*)(go + (size_t)r0 * H3 + n) =
                __floats2half2_rn(c[mf][nf][0] + b0, c[mf][nf][1] + b1);
            *(__half2*)(go + (size_t)(r0 + 8) * H3 + n) =
                __floats2half2_rn(c[mf][nf][2] + b0, c[mf][nf][3] + b1);
        }
    }
}

// ---------------- persistent GRU ----------------
// 128 blocks: dir(2) x mt(8) x jt(8). Group barrier over the 8 jt-blocks
// sharing (dir, mt) — the only blocks whose h rows interact.
__device__ __forceinline__ void group_barrier(int g) {
    __syncthreads();
    if (threadIdx.x == 0) {
        __threadfence();
        const int gi = g * 32;
        unsigned gen = g_ggen[gi];
        if (atomicAdd(&g_gcnt[gi], 1u) == 7u) {
            atomicExch(&g_gcnt[gi], 0u);
            __threadfence();
            g_ggen[gi] = gen + 1u;
        } else {
            while (g_ggen[gi] == gen) { __nanosleep(32); }
            __threadfence();
        }
    }
    __syncthreads();
}

__global__ void __launch_bounds__(256, 1) gru_persist(const float* __restrict__ bhf,
                                                      const float* __restrict__ bhb) {
    extern __shared__ unsigned char smem[];
    __half* Ws = (__half*)smem;                        // 50688
    __half* Ah = (__half*)(smem + 96 * WST * 2);       // 128*264*2 = 67584

    const int tid = threadIdx.x, lane = tid & 31, wid = tid >> 5;
    const int bid = blockIdx.x;
    const int dir = bid >> 6, mt = (bid >> 3) & 7, jt = bid & 7;
    const int grp_id = dir * 8 + mt;
    const int m0 = mt * 128, j0 = jt * 32;
    const int wm0 = (wid >> 1) * 32, wn0c = (wid & 1) * 48;

    load_Ws(Ws, g_Whh16[dir], j0, tid);
    const float* bh = dir ? bhb : bhf;
    const __half* gi = g_gi16[dir];
    __syncthreads();

    const int srow = tid >> 1;                 // staging helpers (row pairs)
    const int jbase = j0 + (wid & 1) * 16 + (lane & 3) * 2;

    for (int s = 0; s < SS; s++) {
        const int par = s & 1;
        const __half* h16 = g_h16[par][dir];
        const float*  h32 = g_h32[par][dir];
        float*  hn32 = g_h32[par ^ 1][dir];
        __half* hn16 = g_h16[par ^ 1][dir];
        const int s_io = dir ? (SS - 1 - s) : s;

        // stage full h tile: 128 rows x 256 halves
        #pragma unroll
        for (int i = 0; i < 16; i++) {
            const int idx = tid + i * 256;
            const int row = idx >> 5, seg = idx & 31;
            *(uint4*)(Ah + row * WST + seg * 8) =
                *(const uint4*)(h16 + (size_t)(m0 + row) * HH + seg * 8);
        }
        __syncthreads();

        float c[2][6][4] = {};
        #pragma unroll
        for (int t = 0; t < 16; t++)
            mma_chunk_32x48<WST>(Ah, Ws, t * 16, t * 16, wm0, wn0c, lane, c);

        // gate math directly on fragments (each thread owns complete triples)
        #pragma unroll
        for (int mf = 0; mf < 2; mf++) {
            const int rb = m0 + wm0 + mf * 16 + (lane >> 2);
            #pragma unroll
            for (int g = 0; g < 2; g++) {
                const int j = jbase + g * 8;
                const float bhr = bh[j],          bhr1 = bh[j + 1];
                const float bhz = bh[HH + j],     bhz1 = bh[HH + j + 1];
                const float bhn = bh[2*HH + j],   bhn1 = bh[2*HH + j + 1];
                #pragma unroll
                for (int rh = 0; rh < 2; rh++) {
                    const int row = rb + rh * 8;
                    const int e = rh * 2;
                    const size_t gb = ((size_t)s_io * BB + row) * H3;
                    const __half2 ih_r = *(const __half2*)(gi + gb + j);
                    const __half2 ih_z = *(const __half2*)(gi + gb + HH + j);
                    const __half2 ih_n = *(const __half2*)(gi + gb + 2*HH + j);
                    const float2 ir = __half22float2(ih_r);
                    const float2 iz = __half22float2(ih_z);
                    const float2 inn = __half22float2(ih_n);
                    const float2 ho = *(const float2*)(h32 + (size_t)row * HH + j);

                    const float r0 = sigmoidf_(ir.x + c[mf][3*g+0][e]   + bhr);
                    const float r1 = sigmoidf_(ir.y + c[mf][3*g+0][e+1] + bhr1);
                    const float z0 = sigmoidf_(iz.x + c[mf][3*g+1][e]   + bhz);
                    const float z1 = sigmoidf_(iz.y + c[mf][3*g+1][e+1] + bhz1);
                    const float n0 = tanhf(inn.x + r0 * (c[mf][3*g+2][e]   + bhn));
                    const float n1 = tanhf(inn.y + r1 * (c[mf][3*g+2][e+1] + bhn1));
                    const float h0 = (1.0f - z0) * n0 + z0 * ho.x;
                    const float h1 = (1.0f - z1) * n1 + z1 * ho.y;

                    *(float2*)(hn32 + (size_t)row * HH + j) = make_float2(h0, h1);
                    const __half2 hh = __floats2half2_rn(h0, h1);
                    *(__half2*)(hn16 + (size_t)row * HH + j) = hh;
                    *(__half2*)(g_f16 + ((size_t)s_io * BB + row) * FF + (size_t)dir * HH + j) = hh;
                }
            }
        }
        group_barrier(grp_id);
    }
}

// ---------------- attention scores (128x128 tile, warp 64x32) ----------------
__global__ void __launch_bounds__(256) attn_mma(const float* __restrict__ wbias,
                                                const float* __restrict__ cw) {
    __shared__ __half As[2][128 * AST];
    __shared__ __half Bs[2][128 * AST];
    __shared__ float part[128];

    const int tid = threadIdx.x, lane = tid & 31, wid = tid >> 5;
    const int m0 = blockIdx.x * 128, n0 = blockIdx.y * 128;
    const int wm0 = (wid >> 2) * 64, wn0 = (wid & 3) * 32;

    if (tid < 128) part[tid] = 0.0f;

    const int arow = tid >> 1, apart = tid & 1;
    const __half* asrc = g_f16 + (size_t)(m0 + arow) * FF + apart * 8;
    const __half* bsrc = g_WwT16 + (size_t)(n0 + arow) * FF + apart * 8;
    uint4 prefA = *(const uint4*)asrc;
    uint4 prefB = *(const uint4*)bsrc;

    float c[4][4][4] = {};
    for (int t = 0; t < 32; t++) {
        *(uint4*)(As[t & 1] + arow * AST + apart * 8) = prefA;
        *(uint4*)(Bs[t & 1] + arow * AST + apart * 8) = prefB;
        __syncthreads();
        if (t < 31) {
            prefA = *(const uint4*)(asrc + (t + 1) * 16);
            prefB = *(const uint4*)(bsrc + (t + 1) * 16);
        }
        uint32_t a[4][4];
        #pragma unroll
        for (int mf = 0; mf < 4; mf++) {
            uint32_t addr = smem_u32(As[t & 1] + (wm0 + mf * 16 + (lane & 15)) * AST + ((lane >> 4) << 3));
            ldsm4(a[mf][0], a[mf][1], a[mf][2], a[mf][3], addr);
        }
        uint32_t b[4][2];
        #pragma unroll
        for (int p = 0; p < 2; p++) {
            uint32_t addr = smem_u32(Bs[t & 1] + (wn0 + p * 16 + (lane & 15)) * AST + ((lane >> 4) << 3));
            uint32_t r0, r1, r2, r3;
            ldsm4(r0, r1, r2, r3, addr);
            b[2*p][0] = r0; b[2*p+1][0] = r1; b[2*p][1] = r2; b[2*p+1][1] = r3;
        }
        #pragma unroll
        for (int mf = 0; mf < 4; mf++)
            #pragma unroll
            for (int nf = 0; nf < 4; nf++)
                mma16816(c[mf][nf], a[mf], b[nf][0], b[nf][1]);
        __syncthreads();
    }

    #pragma unroll
    for (int mf = 0; mf < 4; mf++) {
        const int r = wm0 + mf * 16 + (lane >> 2);
        float v0 = 0.0f, v1 = 0.0f;
        #pragma unroll
        for (int nf = 0; nf < 4; nf++) {
            const int n = n0 + wn0 + nf * 8 + (lane & 3) * 2;
            const float wb0 = wbias[n], wb1 = wbias[n + 1];
            const float c0 = cw[n], c1 = cw[n + 1];
            v0 += tanhf(c[mf][nf][0] + wb0) * c0 + tanhf(c[mf][nf][1] + wb1) * c1;
            v1 += tanhf(c[mf][nf][2] + wb0) * c0 + tanhf(c[mf][nf][3] + wb1) * c1;
        }
        atomicAdd(&part[r], v0);
        atomicAdd(&part[r + 8], v1);
    }
    __syncthreads();
    if (tid < 128) atomicAdd(&g_scores_pre[m0 + tid], part[tid]);
}

// ---------------- softmax over seq (tanh applied inline) ----------------
__global__ void softmax_kernel() {
    int b = blockIdx.x * blockDim.x + threadIdx.x;
    if (b >= BB) return;
    float mx = -1e30f;
    for (int s = 0; s < SS; s++) mx = fmaxf(mx, tanhf(g_scores_pre[s * BB + b]));
    float sum = 0.0f;
    for (int s = 0; s < SS; s++) sum += expf(tanhf(g_scores_pre[s * BB + b]) - mx);
    float inv = 1.0f / sum;
    for (int s = 0; s < SS; s++)
        g_alpha[s * BB + b] = expf(tanhf(g_scores_pre[s * BB + b]) - mx) * inv;
}

// ---------------- pooled + h_output ----------------
__global__ void pool_kernel(float* __restrict__ out) {
    int idx = blockIdx.x * blockDim.x + threadIdx.x;   // over BB*FF/2
    if (idx >= BB * FF / 2) return;
    const int b = idx / (FF / 2), e = (idx % (FF / 2)) * 2;
    float ax = 0.0f, ay = 0.0f;
    for (int s = 0; s < SS; s++) {
        const __half2 v = *(const __half2*)(g_f16 + ((size_t)s * BB + b) * FF + e);
        const float2 f = __half22float2(v);
        const float a = g_alpha[s * BB + b];
        ax += f.x * a; ay += f.y * a;
    }
    out[b * FF + e] = ax;
    out[b * FF + e + 1] = ay;
}

__global__ void hcopy_kernel(float* __restrict__ out) {
    int idx = blockIdx.x * blockDim.x + threadIdx.x;
    if (idx < 2 * BB * HH) out[BB * FF + idx] = (&g_h32[0][0][0])[idx];
}

// ---------------- launch ----------------
extern "C" void kernel_launch(void* const* d_in, const int* in_sizes, int n_in,
                              void* d_out, int out_size) {
    const int*   tokens = (const int*)  d_in[0];
    const float* hidden = (const float*)d_in[1];
    const float* emb    = (const float*)d_in[2];
    const float* W_ih_f = (const float*)d_in[3];
    const float* W_hh_f = (const float*)d_in[4];
    const float* b_ih_f = (const float*)d_in[5];
    const float* b_hh_f = (const float*)d_in[6];
    const float* W_ih_b = (const float*)d_in[7];
    const float* W_hh_b = (const float*)d_in[8];
    const float* b_ih_b = (const float*)d_in[9];
    const float* b_hh_b = (const float*)d_in[10];
    const float* Ww     = (const float*)d_in[11];
    const float* wbias  = (const float*)d_in[12];
    const float* cw     = (const float*)d_in[13];
    float* out = (float*)d_out;

    const int GI_SMEM  = 96 * WST * 2 + 2 * 128 * AST * 2;   // 62976
    const int GRU_SMEM = 96 * WST * 2 + 128 * WST * 2;       // 118272
    cudaFuncSetAttribute(gi_mma,      cudaFuncAttributeMaxDynamicSharedMemorySize, GI_SMEM);
    cudaFuncSetAttribute(gru_persist, cudaFuncAttributeMaxDynamicSharedMemorySize, GRU_SMEM);

    conv_main<<<1024, 256>>>(emb, W_ih_f, W_ih_b, W_hh_f, W_hh_b, Ww, hidden);

    {
        dim3 g(SB / 128, 8, 2);
        gi_mma<<<g, 256, GI_SMEM>>>(tokens, b_ih_f, b_ih_b);
    }

    gru_persist<<<128, 256, GRU_SMEM>>>(b_hh_f, b_hh_b);

    {
        dim3 g(SB / 128, FF / 128);
        attn_mma<<<g, 256>>>(wbias, cw);
    }

    softmax_kernel<<<4, 256>>>();
    pool_kernel<<<(BB * FF / 2 + 255) / 256, 256>>>(out);
    hcopy_kernel<<<(2 * BB * HH + 255) / 256, 256>>>(out);
}

// round 7
// speedup vs baseline: 1.2670x; 1.2670x over previous
#include <cuda_runtime.h>
#include <cuda_fp16.h>
#include <math.h>
#include <stdint.h>

#define SS 128
#define BB 1024
#define EE 256
#define HH 256
#define H3 768
#define FF 512
#define SB (SS*BB)          // 131072
#define VV 50000

#define WST 264    // full-K tile row stride (halves): 256 + pad
#define AST2 72    // 64-chunk tile row stride (halves): 64 + pad

// ---------------- device scratch (no allocs allowed) ----------------
__device__ __half g_emb16[(size_t)VV * EE];
__device__ __half g_Wih16[2][H3 * EE];
__device__ __half g_Whh16[2][H3 * HH];
__device__ __half g_WwT16[FF * FF];           // [n][k] = Ww[k][n]
__device__ __half g_gi16[2][(size_t)SB * H3];
__device__ __half g_f16[(size_t)SB * FF];
__device__ float  g_h32[2][2][BB * HH];       // [pingpong][dir]
__device__ __half g_h16[2][2][BB * HH];
__device__ float  g_scores_pre[SB];
__device__ float  g_alpha[SB];
__device__ unsigned g_gcnt[32 * 32];          // per-group barrier counters (128B apart)
__device__ volatile unsigned g_ggen[32 * 32];

// ---------------- helpers ----------------
__device__ __forceinline__ uint32_t smem_u32(const void* p) {
    return (uint32_t)__cvta_generic_to_shared(p);
}
__device__ __forceinline__ void ldsm4(uint32_t& r0, uint32_t& r1, uint32_t& r2, uint32_t& r3, uint32_t a) {
    asm volatile("ldmatrix.sync.aligned.m8n8.x4.shared.b16 {%0,%1,%2,%3},[%4];"
                 : "=r"(r0), "=r"(r1), "=r"(r2), "=r"(r3) : "r"(a));
}
__device__ __forceinline__ void mma16816(float* c, const uint32_t* a, uint32_t b0, uint32_t b1) {
    asm volatile("mma.sync.aligned.m16n8k16.row.col.f32.f16.f16.f32 "
                 "{%0,%1,%2,%3},{%4,%5,%6,%7},{%8,%9},{%0,%1,%2,%3};"
                 : "+f"(c[0]), "+f"(c[1]), "+f"(c[2]), "+f"(c[3])
                 : "r"(a[0]), "r"(a[1]), "r"(a[2]), "r"(a[3]), "r"(b0), "r"(b1));
}
__device__ __forceinline__ float sigmoidf_(float x) { return 1.0f / (1.0f + __expf(-x)); }
__device__ __forceinline__ float tanh_fast(float x) {
    float y; asm("tanh.approx.f32 %0, %1;" : "=f"(y) : "f"(x)); return y;
}

// Ws: ncols cols, K=256 full, gate/j interleaved so mma frags hold complete triples.
// col c: wslot=c/48, cl=c%48, nf=cl/8, q=cl&7, gate=nf%3, grp=nf/3
//   -> W row = gate*HH + j0 + wslot*16 + grp*8 + q
__device__ __forceinline__ void load_Ws(__half* Ws, const __half* W16, int j0, int tid, int ncols) {
    for (int i = tid; i < ncols * 32; i += 256) {
        const int c = i >> 5, seg = i & 31;
        const int wslot = c / 48, cl = c % 48, nf = cl >> 3, q = cl & 7;
        const int gate = nf % 3, grp = nf / 3;
        const int wrow = gate * HH + j0 + wslot * 16 + grp * 8 + q;
        uint4 v = *(const uint4*)(W16 + (size_t)wrow * 256 + seg * 8);
        *(uint4*)(Ws + c * WST + seg * 8) = v;
    }
}

// warp tile 32x48 (mf=2, nf=6), one k=16 chunk. 2 ldsm4(A) + 3 ldsm4(B) -> 12 mma.
template<int STRIDE>
__device__ __forceinline__ void mma_chunk_32x48(const __half* Atile, const __half* Ws,
                                                int kcA, int kcW, int wm0, int wn0c,
                                                int lane, float (&c)[2][6][4]) {
    uint32_t a[2][4];
    #pragma unroll
    for (int mf = 0; mf < 2; mf++) {
        uint32_t addr = smem_u32(Atile + (wm0 + mf * 16 + (lane & 15)) * STRIDE + kcA + ((lane >> 4) << 3));
        ldsm4(a[mf][0], a[mf][1], a[mf][2], a[mf][3], addr);
    }
    uint32_t b[6][2];
    #pragma unroll
    for (int p = 0; p < 3; p++) {
        uint32_t addr = smem_u32(Ws + (wn0c + p * 16 + (lane & 15)) * WST + kcW + ((lane >> 4) << 3));
        uint32_t r0, r1, r2, r3;
        ldsm4(r0, r1, r2, r3, addr);
        b[2*p][0] = r0; b[2*p+1][0] = r1; b[2*p][1] = r2; b[2*p+1][1] = r3;
    }
    #pragma unroll
    for (int mf = 0; mf < 2; mf++)
        #pragma unroll
        for (int nf = 0; nf < 6; nf++)
            mma16816(c[mf][nf], a[mf], b[nf][0], b[nf][1]);
}

// ---------------- conversions + init ----------------
__global__ void conv_main(const float* __restrict__ emb,
                          const float* __restrict__ Wihf, const float* __restrict__ Wihb,
                          const float* __restrict__ Whhf, const float* __restrict__ Whhb,
                          const float* __restrict__ Ww,   const float* __restrict__ hidden) {
    int i = blockIdx.x * blockDim.x + threadIdx.x;
    int st = gridDim.x * blockDim.x;
    for (size_t j = i; j < (size_t)VV * EE; j += st) g_emb16[j] = __float2half(emb[j]);
    for (int j = i; j < H3 * EE; j += st) {
        g_Wih16[0][j] = __float2half(Wihf[j]);
        g_Wih16[1][j] = __float2half(Wihb[j]);
        g_Whh16[0][j] = __float2half(Whhf[j]);
        g_Whh16[1][j] = __float2half(Whhb[j]);
    }
    for (int j = i; j < FF * FF; j += st) {
        int n = j / FF, k = j % FF;
        g_WwT16[j] = __float2half(Ww[(size_t)k * FF + n]);
    }
    for (int j = i; j < 2 * BB * HH; j += st) {
        float v = hidden[j];
        (&g_h32[0][0][0])[j] = v;
        (&g_h16[0][0][0])[j] = __float2half(v);
    }
    for (int j = i; j < SB; j += st) g_scores_pre[j] = 0.0f;
    if (i < 32 * 32) g_gcnt[i] = 0u;
}

// ---------------- gi = gather(emb,tokens) @ W_ih^T + b_ih  (fp16 out) ----------------
// grid (SB/128, 8, 2); block tile 128 x 96 (gate/j interleaved cols). K chunks of 64.
__global__ void __launch_bounds__(256) gi_mma(const int* __restrict__ tokens,
                                              const float* __restrict__ bif,
                                              const float* __restrict__ bib) {
    extern __shared__ unsigned char smem[];
    __half* Ws = (__half*)smem;                        // 96*WST*2 = 50688
    __half* As = (__half*)(smem + 96 * WST * 2);       // 2 * 128*AST2*2 = 36864
    __shared__ int tok[128];

    const int tid = threadIdx.x, lane = tid & 31, wid = tid >> 5;
    const int m0 = blockIdx.x * 128, j0 = blockIdx.y * 32, dir = blockIdx.z;
    const int wm0 = (wid >> 1) * 32, wn0c = (wid & 1) * 48;

    load_Ws(Ws, g_Wih16[dir], j0, tid, 96);
    if (tid < 128) tok[tid] = tokens[m0 + tid];
    __syncthreads();

    const int srow = tid >> 3, sseg = tid & 7;   // staging: 128 rows x 8 uint4 (64 halves)
    uint4 pa[4];
    #pragma unroll
    for (int i = 0; i < 4; i++)
        pa[i] = *(const uint4*)(g_emb16 + (size_t)tok[srow + i * 32] * EE + sseg * 8);

    float c[2][6][4] = {};
    for (int t = 0; t < 4; t++) {
        __half* Ab = As + (t & 1) * 128 * AST2;
        #pragma unroll
        for (int i = 0; i < 4; i++)
            *(uint4*)(Ab + (srow + i * 32) * AST2 + sseg * 8) = pa[i];
        __syncthreads();
        if (t < 3) {
            #pragma unroll
            for (int i = 0; i < 4; i++)
                pa[i] = *(const uint4*)(g_emb16 + (size_t)tok[srow + i * 32] * EE + (t + 1) * 64 + sseg * 8);
        }
        #pragma unroll
        for (int sub = 0; sub < 4; sub++)
            mma_chunk_32x48<AST2>(Ab, Ws, sub * 16, t * 64 + sub * 16, wm0, wn0c, lane, c);
    }

    const float* bias = dir ? bib : bif;
    __half* go = g_gi16[dir];
    const int jbase = j0 + (wid & 1) * 16 + (lane & 3) * 2;
    #pragma unroll
    for (int mf = 0; mf < 2; mf++) {
        const int r0 = m0 + wm0 + mf * 16 + (lane >> 2);
        #pragma unroll
        for (int nf = 0; nf < 6; nf++) {
            const int gate = nf % 3, grp = nf / 3;
            const int n = gate * HH + jbase + grp * 8;
            const float b0 = bias[n], b1 = bias[n + 1];
            *(__half2*)(go + (size_t)r0 * H3 + n) =
                __floats2half2_rn(c[mf][nf][0] + b0, c[mf][nf][1] + b1);
            *(__half2*)(go + (size_t)(r0 + 8) * H3 + n) =
                __floats2half2_rn(c[mf][nf][2] + b0, c[mf][nf][3] + b1);
        }
    }
}

// ---------------- persistent GRU ----------------
// 128 blocks: dir(2) x mt(16) x jt(4). Block tile: 64 rows x 64 j (192 gate cols).
// Group barrier over the 4 jt-blocks sharing (dir, mt).
__device__ __forceinline__ void group_barrier(int g) {
    __syncthreads();
    if (threadIdx.x == 0) {
        __threadfence();
        const int gi = g * 32;
        unsigned gen = g_ggen[gi];
        if (atomicAdd(&g_gcnt[gi], 1u) == 3u) {
            atomicExch(&g_gcnt[gi], 0u);
            __threadfence();
            g_ggen[gi] = gen + 1u;
        } else {
            while (g_ggen[gi] == gen) { __nanosleep(32); }
            __threadfence();
        }
    }
    __syncthreads();
}

__global__ void __launch_bounds__(256, 1) gru_persist(const float* __restrict__ bhf,
                                                      const float* __restrict__ bhb) {
    extern __shared__ unsigned char smem[];
    __half* Ws = (__half*)smem;                        // 192*WST*2 = 101376
    __half* Ah = (__half*)(smem + 192 * WST * 2);      // 64*WST*2 = 33792

    const int tid = threadIdx.x, lane = tid & 31, wid = tid >> 5;
    const int bid = blockIdx.x;
    const int dir = bid >> 6, mt = (bid >> 2) & 15, jt = bid & 3;
    const int grp_id = dir * 16 + mt;
    const int m0 = mt * 64, j0 = jt * 64;
    const int wm0 = (wid >> 2) * 32, wn0c = (wid & 3) * 48;

    load_Ws(Ws, g_Whh16[dir], j0, tid, 192);
    const float* bh = dir ? bhb : bhf;
    const __half* gi = g_gi16[dir];

    const int jbase = j0 + (wid & 3) * 16 + (lane & 3) * 2;
    // hoist biases out of the step loop: [g][gate][elem]
    float bhv[2][3][2];
    #pragma unroll
    for (int g = 0; g < 2; g++)
        #pragma unroll
        for (int gate = 0; gate < 3; gate++) {
            bhv[g][gate][0] = bh[gate * HH + jbase + g * 8];
            bhv[g][gate][1] = bh[gate * HH + jbase + g * 8 + 1];
        }
    __syncthreads();

    const int srow = tid >> 5, sseg = tid & 31;   // staging: 64 rows x 32 uint4

    for (int s = 0; s < SS; s++) {
        const int par = s & 1;
        const __half* h16 = g_h16[par][dir];
        const float*  h32 = g_h32[par][dir];
        float*  hn32 = g_h32[par ^ 1][dir];
        __half* hn16 = g_h16[par ^ 1][dir];
        const int s_io = dir ? (SS - 1 - s) : s;

        // prefetch epilogue operands (independent of this step's GEMM)
        __half2 pr[2][2][2], pz[2][2][2], pn[2][2][2];
        float2  pho[2][2][2];
        #pragma unroll
        for (int mf = 0; mf < 2; mf++)
            #pragma unroll
            for (int rh = 0; rh < 2; rh++) {
                const int row = m0 + wm0 + mf * 16 + (lane >> 2) + rh * 8;
                const size_t gb = ((size_t)s_io * BB + row) * H3;
                #pragma unroll
                for (int g = 0; g < 2; g++) {
                    const int j = jbase + g * 8;
                    pr[mf][g][rh]  = *(const __half2*)(gi + gb + j);
                    pz[mf][g][rh]  = *(const __half2*)(gi + gb + HH + j);
                    pn[mf][g][rh]  = *(const __half2*)(gi + gb + 2 * HH + j);
                    pho[mf][g][rh] = *(const float2*)(h32 + (size_t)row * HH + j);
                }
            }

        // stage h tile: 64 rows x 256 halves (8 uint4 per thread)
        #pragma unroll
        for (int i = 0; i < 8; i++)
            *(uint4*)(Ah + (srow + i * 8) * WST + sseg * 8) =
                *(const uint4*)(h16 + (size_t)(m0 + srow + i * 8) * HH + sseg * 8);
        __syncthreads();

        float c[2][6][4] = {};
        #pragma unroll
        for (int t = 0; t < 16; t++)
            mma_chunk_32x48<WST>(Ah, Ws, t * 16, t * 16, wm0, wn0c, lane, c);

        // gate math on fragments (each thread owns complete (r,z,n) triples)
        #pragma unroll
        for (int mf = 0; mf < 2; mf++) {
            #pragma unroll
            for (int g = 0; g < 2; g++) {
                const int j = jbase + g * 8;
                #pragma unroll
                for (int rh = 0; rh < 2; rh++) {
                    const int row = m0 + wm0 + mf * 16 + (lane >> 2) + rh * 8;
                    const int e = rh * 2;
                    const float2 ir  = __half22float2(pr[mf][g][rh]);
                    const float2 iz  = __half22float2(pz[mf][g][rh]);
                    const float2 inn = __half22float2(pn[mf][g][rh]);
                    const float2 ho  = pho[mf][g][rh];

                    const float r0 = sigmoidf_(ir.x + c[mf][3*g+0][e]   + bhv[g][0][0]);
                    const float r1 = sigmoidf_(ir.y + c[mf][3*g+0][e+1] + bhv[g][0][1]);
                    const float z0 = sigmoidf_(iz.x + c[mf][3*g+1][e]   + bhv[g][1][0]);
                    const float z1 = sigmoidf_(iz.y + c[mf][3*g+1][e+1] + bhv[g][1][1]);
                    const float n0 = tanhf(inn.x + r0 * (c[mf][3*g+2][e]   + bhv[g][2][0]));
                    const float n1 = tanhf(inn.y + r1 * (c[mf][3*g+2][e+1] + bhv[g][2][1]));
                    const float h0 = (1.0f - z0) * n0 + z0 * ho.x;
                    const float h1 = (1.0f - z1) * n1 + z1 * ho.y;

                    *(float2*)(hn32 + (size_t)row * HH + j) = make_float2(h0, h1);
                    const __half2 hh = __floats2half2_rn(h0, h1);
                    *(__half2*)(hn16 + (size_t)row * HH + j) = hh;
                    *(__half2*)(g_f16 + ((size_t)s_io * BB + row) * FF + (size_t)dir * HH + j) = hh;
                }
            }
        }
        group_barrier(grp_id);
    }
}

// ---------------- attention scores (128x128 tile, warp 64x32, K chunks of 64) ----------------
__global__ void __launch_bounds__(256) attn_mma(const float* __restrict__ wbias,
                                                const float* __restrict__ cw) {
    extern __shared__ unsigned char smem[];
    __half* As = (__half*)smem;                           // 2*128*AST2 halves
    __half* Bs = (__half*)(smem + 2 * 128 * AST2 * 2);    // 2*128*AST2 halves
    __shared__ float part[128];

    const int tid = threadIdx.x, lane = tid & 31, wid = tid >> 5;
    const int m0 = blockIdx.x * 128, n0 = blockIdx.y * 128;
    const int wm0 = (wid >> 2) * 64, wn0 = (wid & 3) * 32;

    if (tid < 128) part[tid] = 0.0f;

    const int srow = tid >> 3, sseg = tid & 7;   // 128 rows x 8 uint4
    const __half* asrc = g_f16 + (size_t)m0 * FF;
    const __half* bsrc = g_WwT16 + (size_t)n0 * FF;

    uint4 pa[4], pb[4];
    #pragma unroll
    for (int i = 0; i < 4; i++) {
        pa[i] = *(const uint4*)(asrc + (size_t)(srow + i * 32) * FF + sseg * 8);
        pb[i] = *(const uint4*)(bsrc + (size_t)(srow + i * 32) * FF + sseg * 8);
    }

    float c[4][4][4] = {};
    for (int t = 0; t < 8; t++) {
        __half* Ab = As + (t & 1) * 128 * AST2;
        __half* Bb = Bs + (t & 1) * 128 * AST2;
        #pragma unroll
        for (int i = 0; i < 4; i++) {
            *(uint4*)(Ab + (srow + i * 32) * AST2 + sseg * 8) = pa[i];
            *(uint4*)(Bb + (srow + i * 32) * AST2 + sseg * 8) = pb[i];
        }
        __syncthreads();
        if (t < 7) {
            #pragma unroll
            for (int i = 0; i < 4; i++) {
                pa[i] = *(const uint4*)(asrc + (size_t)(srow + i * 32) * FF + (t + 1) * 64 + sseg * 8);
                pb[i] = *(const uint4*)(bsrc + (size_t)(srow + i * 32) * FF + (t + 1) * 64 + sseg * 8);
            }
        }
        #pragma unroll
        for (int sub = 0; sub < 4; sub++) {
            const int kc = sub * 16;
            uint32_t a[4][4];
            #pragma unroll
            for (int mf = 0; mf < 4; mf++) {
                uint32_t addr = smem_u32(Ab + (wm0 + mf * 16 + (lane & 15)) * AST2 + kc + ((lane >> 4) << 3));
                ldsm4(a[mf][0], a[mf][1], a[mf][2], a[mf][3], addr);
            }
            uint32_t b[4][2];
            #pragma unroll
            for (int p = 0; p < 2; p++) {
                uint32_t addr = smem_u32(Bb + (wn0 + p * 16 + (lane & 15)) * AST2 + kc + ((lane >> 4) << 3));
                uint32_t r0, r1, r2, r3;
                ldsm4(r0, r1, r2, r3, addr);
                b[2*p][0] = r0; b[2*p+1][0] = r1; b[2*p][1] = r2; b[2*p+1][1] = r3;
            }
            #pragma unroll
            for (int mf = 0; mf < 4; mf++)
                #pragma unroll
                for (int nf = 0; nf < 4; nf++)
                    mma16816(c[mf][nf], a[mf], b[nf][0], b[nf][1]);
        }
    }

    #pragma unroll
    for (int mf = 0; mf < 4; mf++) {
        const int r = wm0 + mf * 16 + (lane >> 2);
        float v0 = 0.0f, v1 = 0.0f;
        #pragma unroll
        for (int nf = 0; nf < 4; nf++) {
            const int n = n0 + wn0 + nf * 8 + (lane & 3) * 2;
            const float wb0 = wbias[n], wb1 = wbias[n + 1];
            const float c0 = cw[n], c1 = cw[n + 1];
            v0 += tanh_fast(c[mf][nf][0] + wb0) * c0 + tanh_fast(c[mf][nf][1] + wb1) * c1;
            v1 += tanh_fast(c[mf][nf][2] + wb0) * c0 + tanh_fast(c[mf][nf][3] + wb1) * c1;
        }
        atomicAdd(&part[r], v0);
        atomicAdd(&part[r + 8], v1);
    }
    __syncthreads();
    if (tid < 128) atomicAdd(&g_scores_pre[m0 + tid], part[tid]);
}

// ---------------- softmax over seq (tanh applied inline) ----------------
__global__ void softmax_kernel() {
    int b = blockIdx.x * blockDim.x + threadIdx.x;
    if (b >= BB) return;
    float mx = -1e30f;
    for (int s = 0; s < SS; s++) {
        float t = tanh_fast(g_scores_pre[s * BB + b]);
        g_alpha[s * BB + b] = t;
        mx = fmaxf(mx, t);
    }
    float sum = 0.0f;
    for (int s = 0; s < SS; s++) {
        float e = __expf(g_alpha[s * BB + b] - mx);
        g_alpha[s * BB + b] = e;
        sum += e;
    }
    float inv = 1.0f / sum;
    for (int s = 0; s < SS; s++) g_alpha[s * BB + b] *= inv;
}

// ---------------- pooled + h_output ----------------
__global__ void pool_kernel(float* __restrict__ out) {
    int idx = blockIdx.x * blockDim.x + threadIdx.x;   // over BB*FF/2
    if (idx >= BB * FF / 2) return;
    const int b = idx / (FF / 2), e = (idx % (FF / 2)) * 2;
    float ax = 0.0f, ay = 0.0f;
    for (int s = 0; s < SS; s++) {
        const __half2 v = *(const __half2*)(g_f16 + ((size_t)s * BB + b) * FF + e);
        const float2 f = __half22float2(v);
        const float a = g_alpha[s * BB + b];
        ax += f.x * a; ay += f.y * a;
    }
    out[b * FF + e] = ax;
    out[b * FF + e + 1] = ay;
}

__global__ void hcopy_kernel(float* __restrict__ out) {
    int idx = blockIdx.x * blockDim.x + threadIdx.x;
    if (idx < 2 * BB * HH) out[BB * FF + idx] = (&g_h32[0][0][0])[idx];
}

// ---------------- launch ----------------
extern "C" void kernel_launch(void* const* d_in, const int* in_sizes, int n_in,
                              void* d_out, int out_size) {
    const int*   tokens = (const int*)  d_in[0];
    const float* hidden = (const float*)d_in[1];
    const float* emb    = (const float*)d_in[2];
    const float* W_ih_f = (const float*)d_in[3];
    const float* W_hh_f = (const float*)d_in[4];
    const float* b_ih_f = (const float*)d_in[5];
    const float* b_hh_f = (const float*)d_in[6];
    const float* W_ih_b = (const float*)d_in[7];
    const float* W_hh_b = (const float*)d_in[8];
    const float* b_ih_b = (const float*)d_in[9];
    const float* b_hh_b = (const float*)d_in[10];
    const float* Ww     = (const float*)d_in[11];
    const float* wbias  = (const float*)d_in[12];
    const float* cw     = (const float*)d_in[13];
    float* out = (float*)d_out;

    const int GI_SMEM   = 96 * WST * 2 + 2 * 128 * AST2 * 2;   // 50688+36864 = 87552
    const int GRU_SMEM  = 192 * WST * 2 + 64 * WST * 2;        // 101376+33792 = 135168
    const int ATTN_SMEM = 4 * 128 * AST2 * 2;                  // 73728
    cudaFuncSetAttribute(gi_mma,      cudaFuncAttributeMaxDynamicSharedMemorySize, GI_SMEM);
    cudaFuncSetAttribute(gru_persist, cudaFuncAttributeMaxDynamicSharedMemorySize, GRU_SMEM);
    cudaFuncSetAttribute(attn_mma,    cudaFuncAttributeMaxDynamicSharedMemorySize, ATTN_SMEM);

    conv_main<<<1024, 256>>>(emb, W_ih_f, W_ih_b, W_hh_f, W_hh_b, Ww, hidden);

    {
        dim3 g(SB / 128, 8, 2);
        gi_mma<<<g, 256, GI_SMEM>>>(tokens, b_ih_f, b_ih_b);
    }

    gru_persist<<<128, 256, GRU_SMEM>>>(b_hh_f, b_hh_b);

    {
        dim3 g(SB / 128, FF / 128);
        attn_mma<<<g, 256, ATTN_SMEM>>>(wbias, cw);
    }

    softmax_kernel<<<4, 256>>>();
    pool_kernel<<<(BB * FF / 2 + 255) / 256, 256>>>(out);
    hcopy_kernel<<<(2 * BB * HH + 255) / 256, 256>>>(out);
}

// round 9
// speedup vs baseline: 1.4687x; 1.1592x over previous
#include <cuda_runtime.h>
#include <cuda_fp16.h>
#include <math.h>
#include <stdint.h>

#define SS 128
#define BB 1024
#define EE 256
#define HH 256
#define H3 768
#define FF 512
#define SB (SS*BB)          // 131072
#define VV 50000

#define WST 264    // full-K tile row stride (halves): 256 + pad
#define AST2 72    // 64-chunk tile row stride (halves): 64 + pad

// ---------------- device scratch (no allocs allowed) ----------------
__device__ __half g_emb16[(size_t)VV * EE];
__device__ __half g_Wih16[2][H3 * EE];
__device__ __half g_Whh16[2][H3 * HH];
__device__ __half g_WwT16[FF * FF];           // [n][k] = Ww[k][n]
__device__ __half g_gi16[2][(size_t)SB * H3];
__device__ __half g_f16[(size_t)SB * FF];
__device__ __half g_h16init[2][BB * HH];
__device__ float  g_scores_pre[SB];
__device__ float  g_alpha[SB];

// ---------------- helpers ----------------
__device__ __forceinline__ uint32_t smem_u32(const void* p) {
    return (uint32_t)__cvta_generic_to_shared(p);
}
__device__ __forceinline__ void ldsm4(uint32_t& r0, uint32_t& r1, uint32_t& r2, uint32_t& r3, uint32_t a) {
    asm volatile("ldmatrix.sync.aligned.m8n8.x4.shared.b16 {%0,%1,%2,%3},[%4];"
                 : "=r"(r0), "=r"(r1), "=r"(r2), "=r"(r3) : "r"(a));
}
__device__ __forceinline__ void mma16816(float* c, const uint32_t* a, uint32_t b0, uint32_t b1) {
    asm volatile("mma.sync.aligned.m16n8k16.row.col.f32.f16.f16.f32 "
                 "{%0,%1,%2,%3},{%4,%5,%6,%7},{%8,%9},{%0,%1,%2,%3};"
                 : "+f"(c[0]), "+f"(c[1]), "+f"(c[2]), "+f"(c[3])
                 : "r"(a[0]), "r"(a[1]), "r"(a[2]), "r"(a[3]), "r"(b0), "r"(b1));
}
__device__ __forceinline__ void cp_async16(uint32_t dst, const void* src) {
    asm volatile("cp.async.cg.shared.global [%0], [%1], 16;" :: "r"(dst), "l"(src));
}
__device__ __forceinline__ void cp_commit() { asm volatile("cp.async.commit_group;"); }
__device__ __forceinline__ void cp_wait0() { asm volatile("cp.async.wait_group 0;"); }
__device__ __forceinline__ void cp_wait1() { asm volatile("cp.async.wait_group 1;"); }
__device__ __forceinline__ float sigmoidf_(float x) { return 1.0f / (1.0f + __expf(-x)); }
__device__ __forceinline__ float tanh_fast(float x) {
    float y; asm("tanh.approx.f32 %0, %1;" : "=f"(y) : "f"(x)); return y;
}

// Ws: ncols cols, K=256 full, gate/j interleaved so mma frags hold complete triples.
__device__ __forceinline__ void load_Ws(__half* Ws, const __half* W16, int j0, int tid, int ncols) {
    for (int i = tid; i < ncols * 32; i += 256) {
        const int c = i >> 5, seg = i & 31;
        const int wslot = c / 48, cl = c % 48, nf = cl >> 3, q = cl & 7;
        const int gate = nf % 3, grp = nf / 3;
        const int wrow = gate * HH + j0 + wslot * 16 + grp * 8 + q;
        uint4 v = *(const uint4*)(W16 + (size_t)wrow * 256 + seg * 8);
        *(uint4*)(Ws + c * WST + seg * 8) = v;
    }
}

// warp tile 32x48 (mf=2, nf=6), one k=16 chunk. 2 ldsm4(A) + 3 ldsm4(B) -> 12 mma.
template<int STRIDE>
__device__ __forceinline__ void mma_chunk_32x48(const __half* Atile, const __half* Ws,
                                                int kcA, int kcW, int wm0, int wn0c,
                                                int lane, float (&c)[2][6][4]) {
    uint32_t a[2][4];
    #pragma unroll
    for (int mf = 0; mf < 2; mf++) {
        uint32_t addr = smem_u32(Atile + (wm0 + mf * 16 + (lane & 15)) * STRIDE + kcA + ((lane >> 4) << 3));
        ldsm4(a[mf][0], a[mf][1], a[mf][2], a[mf][3], addr);
    }
    uint32_t b[6][2];
    #pragma unroll
    for (int p = 0; p < 3; p++) {
        uint32_t addr = smem_u32(Ws + (wn0c + p * 16 + (lane & 15)) * WST + kcW + ((lane >> 4) << 3));
        uint32_t r0, r1, r2, r3;
        ldsm4(r0, r1, r2, r3, addr);
        b[2*p][0] = r0; b[2*p+1][0] = r1; b[2*p][1] = r2; b[2*p+1][1] = r3;
    }
    #pragma unroll
    for (int mf = 0; mf < 2; mf++)
        #pragma unroll
        for (int nf = 0; nf < 6; nf++)
            mma16816(c[mf][nf], a[mf], b[nf][0], b[nf][1]);
}

// ---------------- conversions + init ----------------
__global__ void conv_main(const float* __restrict__ emb,
                          const float* __restrict__ Wihf, const float* __restrict__ Wihb,
                          const float* __restrict__ Whhf, const float* __restrict__ Whhb,
                          const float* __restrict__ Ww,   const float* __restrict__ hidden) {
    int i = blockIdx.x * blockDim.x + threadIdx.x;
    int st = gridDim.x * blockDim.x;
    for (size_t j = i; j < (size_t)VV * EE; j += st) g_emb16[j] = __float2half(emb[j]);
    for (int j = i; j < H3 * EE; j += st) {
        g_Wih16[0][j] = __float2half(Wihf[j]);
        g_Wih16[1][j] = __float2half(Wihb[j]);
        g_Whh16[0][j] = __float2half(Whhf[j]);
        g_Whh16[1][j] = __float2half(Whhb[j]);
    }
    for (int j = i; j < FF * FF; j += st) {
        int n = j / FF, k = j % FF;
        g_WwT16[j] = __float2half(Ww[(size_t)k * FF + n]);
    }
    for (int j = i; j < 2 * BB * HH; j += st)
        (&g_h16init[0][0])[j] = __float2half(hidden[j]);
    for (int j = i; j < SB; j += st) g_scores_pre[j] = 0.0f;
}

// ---------------- gi = gather(emb,tokens) @ W_ih^T + b_ih  (fp16 out) ----------------
// grid (SB/128, 8, 2); block tile 128 x 96. K chunks of 64, cp.async double buffer.
__global__ void __launch_bounds__(256) gi_mma(const int* __restrict__ tokens,
                                              const float* __restrict__ bif,
                                              const float* __restrict__ bib) {
    extern __shared__ unsigned char smem[];
    __half* Ws = (__half*)smem;                        // 96*WST*2 = 50688
    __half* As = (__half*)(smem + 96 * WST * 2);       // 2 * 128*AST2*2 = 36864
    __shared__ int tok[128];

    const int tid = threadIdx.x, lane = tid & 31, wid = tid >> 5;
    const int m0 = blockIdx.x * 128, j0 = blockIdx.y * 32, dir = blockIdx.z;
    const int wm0 = (wid >> 1) * 32, wn0c = (wid & 1) * 48;

    load_Ws(Ws, g_Wih16[dir], j0, tid, 96);
    if (tid < 128) tok[tid] = tokens[m0 + tid];
    __syncthreads();

    const int srow = tid >> 3, sseg = tid & 7;   // 128 rows x 8 x 16B per buffer
    const uint32_t as_base = smem_u32(As);

    auto stage = [&](int t) {
        const uint32_t dst0 = as_base + ((t & 1) * 128 * AST2 + sseg * 8) * 2;
        #pragma unroll
        for (int i = 0; i < 4; i++) {
            const int row = srow + i * 32;
            cp_async16(dst0 + row * (AST2 * 2),
                       g_emb16 + (size_t)tok[row] * EE + t * 64 + sseg * 8);
        }
        cp_commit();
    };

    stage(0);
    float c[2][6][4] = {};
    for (int t = 0; t < 4; t++) {
        if (t < 3) { stage(t + 1); cp_wait1(); } else cp_wait0();
        __syncthreads();
        const __half* Ab = As + (t & 1) * 128 * AST2;
        #pragma unroll
        for (int sub = 0; sub < 4; sub++)
            mma_chunk_32x48<AST2>(Ab, Ws, sub * 16, t * 64 + sub * 16, wm0, wn0c, lane, c);
        __syncthreads();
    }

    const float* bias = dir ? bib : bif;
    __half* go = g_gi16[dir];
    const int jbase = j0 + (wid & 1) * 16 + (lane & 3) * 2;
    #pragma unroll
    for (int mf = 0; mf < 2; mf++) {
        const int r0 = m0 + wm0 + mf * 16 + (lane >> 2);
        #pragma unroll
        for (int nf = 0; nf < 6; nf++) {
            const int gate = nf % 3, grp = nf / 3;
            const int n = gate * HH + jbase + grp * 8;
            const float b0 = bias[n], b1 = bias[n + 1];
            *(__half2*)(go + (size_t)r0 * H3 + n) =
                __floats2half2_rn(c[mf][nf][0] + b0, c[mf][nf][1] + b1);
            *(__half2*)(go + (size_t)(r0 + 8) * H3 + n) =
                __floats2half2_rn(c[mf][nf][2] + b0, c[mf][nf][3] + b1);
        }
    }
}

// ---------------- persistent GRU: clusters of 4, register-resident h ----------------
// 128 blocks: dir(2) x mt(16) x jt(4); bid = ((dir*16+mt)*4)+jt so a cluster = one jt group.
__global__ void __launch_bounds__(256, 1) __cluster_dims__(4, 1, 1)
gru_persist(const float* __restrict__ bhf, const float* __restrict__ bhb,
            const float* __restrict__ hidden, float* __restrict__ out) {
    extern __shared__ unsigned char smem[];
    __half* Ws = (__half*)smem;                        // 192*WST*2 = 101376
    __half* Ah = (__half*)(smem + 192 * WST * 2);      // 64*WST*2 = 33792

    const int tid = threadIdx.x, lane = tid & 31, wid = tid >> 5;
    const int bid = blockIdx.x;
    const int dir = bid >> 6, mt = (bid >> 2) & 15;
    const int m0 = mt * 64, j0 = (bid & 3) * 64;
    const int wm0 = (wid >> 2) * 32, wn0c = (wid & 3) * 48;

    load_Ws(Ws, g_Whh16[dir], j0, tid, 192);
    const float* bh = dir ? bhb : bhf;
    const __half* gi = g_gi16[dir];

    const int jbase = j0 + (wid & 3) * 16 + (lane & 3) * 2;
    float bhv[2][3][2];
    #pragma unroll
    for (int g = 0; g < 2; g++)
        #pragma unroll
        for (int gate = 0; gate < 3; gate++) {
            bhv[g][gate][0] = bh[gate * HH + jbase + g * 8];
            bhv[g][gate][1] = bh[gate * HH + jbase + g * 8 + 1];
        }

    // register-resident h_old (each thread re-reads exactly what it wrote)
    float2 ho[2][2][2];
    #pragma unroll
    for (int mf = 0; mf < 2; mf++)
        #pragma unroll
        for (int rh = 0; rh < 2; rh++) {
            const int row = m0 + wm0 + mf * 16 + (lane >> 2) + rh * 8;
            #pragma unroll
            for (int g = 0; g < 2; g++)
                ho[mf][g][rh] = *(const float2*)(hidden + ((size_t)dir * BB + row) * HH + jbase + g * 8);
        }

    __half2 pr[2][2][2], pz[2][2][2], pn[2][2][2];
    auto prefetch_gi = [&](int sio) {
        #pragma unroll
        for (int mf = 0; mf < 2; mf++)
            #pragma unroll
            for (int rh = 0; rh < 2; rh++) {
                const int row = m0 + wm0 + mf * 16 + (lane >> 2) + rh * 8;
                const size_t gb = ((size_t)sio * BB + row) * H3;
                #pragma unroll
                for (int g = 0; g < 2; g++) {
                    pr[mf][g][rh] = *(const __half2*)(gi + gb + jbase + g * 8);
                    pz[mf][g][rh] = *(const __half2*)(gi + gb + HH + jbase + g * 8);
                    pn[mf][g][rh] = *(const __half2*)(gi + gb + 2 * HH + jbase + g * 8);
                }
            }
    };
    prefetch_gi(dir ? SS - 1 : 0);
    __syncthreads();

    const int srow = tid >> 5, sseg = tid & 31;   // 64 rows x 32 x 16B
    const uint32_t ah_base = smem_u32(Ah);

    for (int s = 0; s < SS; s++) {
        const int s_io = dir ? (SS - 1 - s) : s;

        // stage h tile from previous step's f16 output (or init)
        {
            const __half* hb;
            size_t hstride;
            if (s == 0) { hb = g_h16init[dir]; hstride = HH; }
            else {
                const int prev_io = dir ? (SS - s) : (s - 1);
                hb = g_f16 + (size_t)prev_io * BB * FF + (size_t)dir * HH;
                hstride = FF;
            }
            #pragma unroll
            for (int i = 0; i < 8; i++) {
                const int row = srow + i * 8;
                cp_async16(ah_base + (row * WST + sseg * 8) * 2,
                           hb + (size_t)(m0 + row) * hstride + sseg * 8);
            }
            cp_commit(); cp_wait0();
        }
        __syncthreads();

        float c[2][6][4] = {};
        #pragma unroll
        for (int t = 0; t < 16; t++)
            mma_chunk_32x48<WST>(Ah, Ws, t * 16, t * 16, wm0, wn0c, lane, c);

        // gate math on fragments; h_old in registers
        #pragma unroll
        for (int mf = 0; mf < 2; mf++) {
            #pragma unroll
            for (int g = 0; g < 2; g++) {
                const int j = jbase + g * 8;
                #pragma unroll
                for (int rh = 0; rh < 2; rh++) {
                    const int row = m0 + wm0 + mf * 16 + (lane >> 2) + rh * 8;
                    const int e = rh * 2;
                    const float2 ir  = __half22float2(pr[mf][g][rh]);
                    const float2 iz  = __half22float2(pz[mf][g][rh]);
                    const float2 inn = __half22float2(pn[mf][g][rh]);
                    const float2 hov = ho[mf][g][rh];

                    const float r0 = sigmoidf_(ir.x + c[mf][3*g+0][e]   + bhv[g][0][0]);
                    const float r1 = sigmoidf_(ir.y + c[mf][3*g+0][e+1] + bhv[g][0][1]);
                    const float z0 = sigmoidf_(iz.x + c[mf][3*g+1][e]   + bhv[g][1][0]);
                    const float z1 = sigmoidf_(iz.y + c[mf][3*g+1][e+1] + bhv[g][1][1]);
                    const float n0 = tanhf(inn.x + r0 * (c[mf][3*g+2][e]   + bhv[g][2][0]));
                    const float n1 = tanhf(inn.y + r1 * (c[mf][3*g+2][e+1] + bhv[g][2][1]));
                    const float h0 = (1.0f - z0) * n0 + z0 * hov.x;
                    const float h1 = (1.0f - z1) * n1 + z1 * hov.y;

                    ho[mf][g][rh] = make_float2(h0, h1);
                    *(__half2*)(g_f16 + ((size_t)s_io * BB + row) * FF + (size_t)dir * HH + j) =
                        __floats2half2_rn(h0, h1);
                    if (s == SS - 1)
                        *(float2*)(out + BB * FF + ((size_t)dir * BB + row) * HH + j) = make_float2(h0, h1);
                }
            }
        }
        __syncthreads();             // all lanes done reading Ah before next overwrite
        __threadfence();
        asm volatile("barrier.cluster.arrive.aligned;" ::: "memory");
        if (s + 1 < SS) prefetch_gi(dir ? (SS - 2 - s) : (s + 1));
        asm volatile("barrier.cluster.wait.aligned;" ::: "memory");
    }
}

// ---------------- attention scores (128x128 tile, warp 64x32, cp.async pipeline) ----------------
__global__ void __launch_bounds__(256) attn_mma(const float* __restrict__ wbias,
                                                const float* __restrict__ cw) {
    extern __shared__ unsigned char smem[];
    __half* As = (__half*)smem;                           // 2*128*AST2 halves
    __half* Bs = (__half*)(smem + 2 * 128 * AST2 * 2);    // 2*128*AST2 halves
    __shared__ float part[128];

    const int tid = threadIdx.x, lane = tid & 31, wid = tid >> 5;
    const int m0 = blockIdx.x * 128, n0 = blockIdx.y * 128;
    const int wm0 = (wid >> 2) * 64, wn0 = (wid & 3) * 32;

    if (tid < 128) part[tid] = 0.0f;

    const int srow = tid >> 3, sseg = tid & 7;   // 128 rows x 8 x 16B
    const __half* asrc = g_f16 + (size_t)m0 * FF;
    const __half* bsrc = g_WwT16 + (size_t)n0 * FF;
    const uint32_t as_base = smem_u32(As), bs_base = smem_u32(Bs);

    auto stage = [&](int t) {
        const uint32_t off = ((t & 1) * 128 * AST2 + sseg * 8) * 2;
        #pragma unroll
        for (int i = 0; i < 4; i++) {
            const int row = srow + i * 32;
            cp_async16(as_base + off + row * (AST2 * 2),
                       asrc + (size_t)row * FF + t * 64 + sseg * 8);
            cp_async16(bs_base + off + row * (AST2 * 2),
                       bsrc + (size_t)row * FF + t * 64 + sseg * 8);
        }
        cp_commit();
    };

    stage(0);
    float c[4][4][4] = {};
    for (int t = 0; t < 8; t++) {
        if (t < 7) { stage(t + 1); cp_wait1(); } else cp_wait0();
        __syncthreads();
        const __half* Ab = As + (t & 1) * 128 * AST2;
        const __half* Bb = Bs + (t & 1) * 128 * AST2;
        #pragma unroll
        for (int sub = 0; sub < 4; sub++) {
            const int kc = sub * 16;
            uint32_t a[4][4];
            #pragma unroll
            for (int mf = 0; mf < 4; mf++) {
                uint32_t addr = smem_u32(Ab + (wm0 + mf * 16 + (lane & 15)) * AST2 + kc + ((lane >> 4) << 3));
                ldsm4(a[mf][0], a[mf][1], a[mf][2], a[mf][3], addr);
            }
            uint32_t b[4][2];
            #pragma unroll
            for (int p = 0; p < 2; p++) {
                uint32_t addr = smem_u32(Bb + (wn0 + p * 16 + (lane & 15)) * AST2 + kc + ((lane >> 4) << 3));
                uint32_t r0, r1, r2, r3;
                ldsm4(r0, r1, r2, r3, addr);
                b[2*p][0] = r0; b[2*p+1][0] = r1; b[2*p][1] = r2; b[2*p+1][1] = r3;
            }
            #pragma unroll
            for (int mf = 0; mf < 4; mf++)
                #pragma unroll
                for (int nf = 0; nf < 4; nf++)
                    mma16816(c[mf][nf], a[mf], b[nf][0], b[nf][1]);
        }
        __syncthreads();
    }

    #pragma unroll
    for (int mf = 0; mf < 4; mf++) {
        const int r = wm0 + mf * 16 + (lane >> 2);
        float v0 = 0.0f, v1 = 0.0f;
        #pragma unroll
        for (int nf = 0; nf < 4; nf++) {
            const int n = n0 + wn0 + nf * 8 + (lane & 3) * 2;
            const float wb0 = wbias[n], wb1 = wbias[n + 1];
            const float c0 = cw[n], c1 = cw[n + 1];
            v0 += tanh_fast(c[mf][nf][0] + wb0) * c0 + tanh_fast(c[mf][nf][1] + wb1) * c1;
            v1 += tanh_fast(c[mf][nf][2] + wb0) * c0 + tanh_fast(c[mf][nf][3] + wb1) * c1;
        }
        atomicAdd(&part[r], v0);
        atomicAdd(&part[r + 8], v1);
    }
    __syncthreads();
    if (tid < 128) atomicAdd(&g_scores_pre[m0 + tid], part[tid]);
}

// ---------------- softmax over seq (tanh applied inline) ----------------
__global__ void softmax_kernel() {
    int b = blockIdx.x * blockDim.x + threadIdx.x;
    if (b >= BB) return;
    float mx = -1e30f;
    for (int s = 0; s < SS; s++) {
        float t = tanh_fast(g_scores_pre[s * BB + b]);
        g_alpha[s * BB + b] = t;
        mx = fmaxf(mx, t);
    }
    float sum = 0.0f;
    for (int s = 0; s < SS; s++) {
        float e = __expf(g_alpha[s * BB + b] - mx);
        g_alpha[s * BB + b] = e;
        sum += e;
    }
    float inv = 1.0f / sum;
    for (int s = 0; s < SS; s++) g_alpha[s * BB + b] *= inv;
}

// ---------------- pooled ----------------
__global__ void pool_kernel(float* __restrict__ out) {
    int idx = blockIdx.x * blockDim.x + threadIdx.x;   // over BB*FF/2
    if (idx >= BB * FF / 2) return;
    const int b = idx / (FF / 2), e = (idx % (FF / 2)) * 2;
    float ax = 0.0f, ay = 0.0f;
    for (int s = 0; s < SS; s++) {
        const __half2 v = *(const __half2*)(g_f16 + ((size_t)s * BB + b) * FF + e);
        const float2 f = __half22float2(v);
        const float a = g_alpha[s * BB + b];
        ax += f.x * a; ay += f.y * a;
    }
    out[b * FF + e] = ax;
    out[b * FF + e + 1] = ay;
}

// ---------------- launch ----------------
extern "C" void kernel_launch(void* const* d_in, const int* in_sizes, int n_in,
                              void* d_out, int out_size) {
    const int*   tokens = (const int*)  d_in[0];
    const float* hidden = (const float*)d_in[1];
    const float* emb    = (const float*)d_in[2];
    const float* W_ih_f = (const float*)d_in[3];
    const float* W_hh_f = (const float*)d_in[4];
    const float* b_ih_f = (const float*)d_in[5];
    const float* b_hh_f = (const float*)d_in[6];
    const float* W_ih_b = (const float*)d_in[7];
    const float* W_hh_b = (const float*)d_in[8];
    const float* b_ih_b = (const float*)d_in[9];
    const float* b_hh_b = (const float*)d_in[10];
    const float* Ww     = (const float*)d_in[11];
    const float* wbias  = (const float*)d_in[12];
    const float* cw     = (const float*)d_in[13];
    float* out = (float*)d_out;

    const int GI_SMEM   = 96 * WST * 2 + 2 * 128 * AST2 * 2;   // 87552
    const int GRU_SMEM  = 192 * WST * 2 + 64 * WST * 2;        // 135168
    const int ATTN_SMEM = 4 * 128 * AST2 * 2;                  // 73728
    cudaFuncSetAttribute(gi_mma,      cudaFuncAttributeMaxDynamicSharedMemorySize, GI_SMEM);
    cudaFuncSetAttribute(gru_persist, cudaFuncAttributeMaxDynamicSharedMemorySize, GRU_SMEM);
    cudaFuncSetAttribute(attn_mma,    cudaFuncAttributeMaxDynamicSharedMemorySize, ATTN_SMEM);

    conv_main<<<1024, 256>>>(emb, W_ih_f, W_ih_b, W_hh_f, W_hh_b, Ww, hidden);

    {
        dim3 g(SB / 128, 8, 2);
        gi_mma<<<g, 256, GI_SMEM>>>(tokens, b_ih_f, b_ih_b);
    }

    gru_persist<<<128, 256, GRU_SMEM>>>(b_hh_f, b_hh_b, hidden, out);

    {
        dim3 g(SB / 128, FF / 128);
        attn_mma<<<g, 256, ATTN_SMEM>>>(wbias, cw);
    }

    softmax_kernel<<<4, 256>>>();
    pool_kernel<<<(BB * FF / 2 + 255) / 256, 256>>>(out);
}